// round 6
// baseline (speedup 1.0000x reference)
#include <cuda_runtime.h>

// EKVNonLinearConv via u-space piecewise-linear table.
//   f(d) = sp(min(a,20))^2 - sp(min(a-D,20))^2, a=d/0.075, D=0.1/0.075
//   d = vg - th ; u = (d - D0)/RANGE clamped to [0,1] by free saturate modifier.
//   Table: f ~= a1*u + a0 on interval idx = floor(u*516). Entries >= 512 are exact zero
//   (f == 0 for d >= 1.6). Kinks d=1.5 -> idx 492, d=1.6 -> idx 512 (on-grid).
//   out = ALPHA*R*scale * sum_l f.

#define CIN    16
#define COUTT  64
#define HH     32
#define WW     32
#define BB     8
#define CG     4      // couts per block
#define RPB    8      // output rows per block
#define NTHR   256    // 8 warps, one output row per warp
#define LPC    144    // CIN*3*3

#define TABN   516               // intervals over d in [-0.96, 1.62], h = 0.005
#define TABEXT 518               // 517 used (idx 0..516) + pad for float4 copy
#define TD0    (-0.96f)
#define TH     0.005f
#define RANGE  2.58f             // 516 * h
#define INVR   0.3875968992248062f   // 1/2.58
#define USCALE 516.0f

__device__ float2 g_tab[TABEXT]; // (a0, a1): f ~= a1*u + a0 on interval i

__device__ __forceinline__ float ekv_exact(float d) {
    const float INVD  = 13.333333333333334f;
    const float DELTA = 1.3333333333333333f;
    float a  = d * INVD;
    float a1 = fminf(fmaxf(a, -50.0f), 20.0f);
    float a2 = fminf(fmaxf(a - DELTA, -50.0f), 20.0f);
    float l1 = log1pf(expf(a1));
    float l2 = log1pf(expf(a2));
    return fmaf(l1, l1, -l2 * l2);
}

__global__ void build_table_kernel() {
    int i = blockIdx.x * blockDim.x + threadIdx.x;
    if (i < TABEXT) {
        float f0 = ekv_exact(TD0 + (float)i * TH);
        float f1 = ekv_exact(TD0 + (float)(i + 1) * TH);
        float a1 = (f1 - f0) * USCALE;           // slope in u-space
        float u0 = (float)i * (1.0f / USCALE);
        g_tab[i] = make_float2(fmaf(-a1, u0, f0), a1);   // i>=512: exact (0,0)
    }
}

__global__ __launch_bounds__(NTHR)
void ekv_conv_kernel(const float* __restrict__ x,
                     const float* __restrict__ theta,
                     const float* __restrict__ scale,
                     float* __restrict__ out)
{
    __shared__ float  sx[CIN][RPB + 2][34];     // halo tile (21.75 KB)
    __shared__ float4 stb[CG][CIN * 3];         // (tb_kx0,tb_kx1,tb_kx2,pad), tb=(0.96-th)/2.58
    __shared__ float  sthr[CIN][RPB + 2];       // per-(ci,row) skip threshold in tb-space
    __shared__ float2 tab[TABEXT];              // ~4 KB

    const int rt = blockIdx.x;       // row tile 0..3
    const int cg = blockIdx.y;       // cout group 0..15
    const int b  = blockIdx.z;       // batch
    const int y0 = rt * RPB;
    const int c0 = cg * CG;
    const int tid = threadIdx.x;

    // ---- copy table from global (L2-hot) ----
    {
        const float4* src = (const float4*)g_tab;
        float4*       dst = (float4*)tab;
        for (int i = tid; i < TABEXT / 2; i += NTHR) dst[i] = src[i];
    }

    // ---- load x halo tile (zero-padded) ----
    for (int i = tid; i < CIN * (RPB + 2) * 34; i += NTHR) {
        int cc = i % 34;
        int r  = (i / 34) % (RPB + 2);
        int ci = i / (34 * (RPB + 2));
        int gy = y0 - 1 + r;
        int gx = cc - 1;
        float v = 0.0f;
        if (gy >= 0 && gy < HH && gx >= 0 && gx < WW)
            v = x[((b * CIN + ci) * HH + gy) * WW + gx];
        sx[ci][r][cc] = v;
    }
    // ---- load theta, transform to tb-space, pack kx-triples as float4 ----
    for (int i = tid; i < CG * CIN * 3; i += NTHR) {
        int g = i % (CIN * 3);           // ci*3 + ky
        int c = i / (CIN * 3);
        const float* tp = theta + (c0 + c) * LPC + g * 3;
        float t0 = fminf(fmaxf(tp[0], 1.0f), 8.0f);
        float t1 = fminf(fmaxf(tp[1], 1.0f), 8.0f);
        float t2 = fminf(fmaxf(tp[2], 1.0f), 8.0f);
        stb[c][g] = make_float4((0.96f - t0) * INVR,
                                (0.96f - t1) * INVR,
                                (0.96f - t2) * INVR, 0.0f);
    }
    __syncthreads();

    // ---- per-(ci,row) skip threshold: active iff tb > (0.11 - rowmax)/2.58 ----
    if (tid < CIN * (RPB + 2)) {
        int r  = tid % (RPB + 2);
        int ci = tid / (RPB + 2);
        float m = -1e30f;
        #pragma unroll
        for (int cc = 0; cc < 34; cc++) m = fmaxf(m, sx[ci][r][cc]);
        sthr[ci][r] = (0.11f - m) * INVR;
    }
    __syncthreads();

    const int tx = tid & 31;    // output column
    const int ty = tid >> 5;    // output row within tile (warp id 0..7)

    float acc[CG];
    #pragma unroll
    for (int c = 0; c < CG; c++) acc[c] = 0.0f;

    #pragma unroll 1
    for (int ci = 0; ci < CIN; ci++) {
        #pragma unroll 1
        for (int ky = 0; ky < 3; ky++) {
            const float tthr = sthr[ci][ty + ky];          // warp-uniform
            const float vg0 = sx[ci][ty + ky][tx + 0];
            const float vg1 = sx[ci][ty + ky][tx + 1];
            const float vg2 = sx[ci][ty + ky][tx + 2];
            const int g = ci * 3 + ky;
            #pragma unroll
            for (int c = 0; c < CG; c++) {
                float4 tb = stb[c][g];                     // 1 LDS.128, warp-uniform
                if (tb.x > tthr) {
                    float u = __saturatef(fmaf(vg0, INVR, tb.x));
                    int idx = __float2int_rd(u * USCALE);
                    float2 e = tab[idx];
                    acc[c] += fmaf(e.y, u, e.x);
                }
                if (tb.y > tthr) {
                    float u = __saturatef(fmaf(vg1, INVR, tb.y));
                    int idx = __float2int_rd(u * USCALE);
                    float2 e = tab[idx];
                    acc[c] += fmaf(e.y, u, e.x);
                }
                if (tb.z > tthr) {
                    float u = __saturatef(fmaf(vg2, INVR, tb.z));
                    int idx = __float2int_rd(u * USCALE);
                    float2 e = tab[idx];
                    acc[c] += fmaf(e.y, u, e.x);
                }
            }
        }
    }

    const float sc = scale[0] * (0.05625f * 0.1f);   // ALPHA * R * scale
    const int y = y0 + ty;
    #pragma unroll
    for (int c = 0; c < CG; c++) {
        out[((b * COUTT + (c0 + c)) * HH + y) * WW + tx] = acc[c] * sc;
    }
}

extern "C" void kernel_launch(void* const* d_in, const int* in_sizes, int n_in,
                              void* d_out, int out_size) {
    const float* x     = (const float*)d_in[0];
    const float* theta = (const float*)d_in[1];
    const float* scale = (const float*)d_in[2];
    float* out = (float*)d_out;
    (void)in_sizes; (void)n_in; (void)out_size;

    build_table_kernel<<<3, 256>>>();

    dim3 grid(HH / RPB, COUTT / CG, BB);   // 4 x 16 x 8 = 512 blocks
    dim3 block(NTHR);
    ekv_conv_kernel<<<grid, block>>>(x, theta, scale, out);
}